// round 11
// baseline (speedup 1.0000x reference)
#include <cuda_runtime.h>
#include <cuda_fp16.h>

#define IN_F   128
#define HEADS  8
#define HC     16   // HEADS * OUT_C
#define NMAX   100000
#define NT     128   // threads per CTA in node_kernel
#define NPC    256   // nodes per CTA (2 per thread)
#define KT     32    // k-tile width
#define XPAD   36    // padded row stride (floats)

// Static scratch (no allocations allowed)
__device__ __align__(128) __half2 g_hh[NMAX * 8];     // h in fp16: 32B per node row
__device__ __align__(128) float g_asrc[NMAX * HEADS]; // 32B per node row
__device__ __align__(128) float g_adst[NMAX * HEADS]; // 32B per node row
__device__ __align__(16)  float g_acc[NMAX * 24];     // per node: S[16] then Z[8]

// FFMA-only exp: exp(x) = 2^(x*log2e). |x| small here, rel err ~2e-6.
__device__ __forceinline__ float fexp(float x) {
    float y = x * 1.44269504f;
    float r = rintf(y);
    float f = y - r;
    float p = 1.3333558e-3f;
    p = fmaf(p, f, 9.6181291e-3f);
    p = fmaf(p, f, 5.5504109e-2f);
    p = fmaf(p, f, 2.4022651e-1f);
    p = fmaf(p, f, 6.9314718e-1f);
    p = fmaf(p, f, 1.0f);
    return __int_as_float(__float_as_int(p) + ((int)r << 23));
}

__device__ __forceinline__ float leaky(float l) {
    return fmaxf(l, 0.f) + 0.2f * fminf(l, 0.f);
}

// Per-node tail: h(fp16) + attention dots + self-loop acc init.
__device__ __forceinline__ void node_tail(int n, const float* acc, const float* s_att) {
    uint4 u0, u1;
    __half2 t;
    t = __floats2half2_rn(acc[0],  acc[1]);  u0.x = *(unsigned*)&t;
    t = __floats2half2_rn(acc[2],  acc[3]);  u0.y = *(unsigned*)&t;
    t = __floats2half2_rn(acc[4],  acc[5]);  u0.z = *(unsigned*)&t;
    t = __floats2half2_rn(acc[6],  acc[7]);  u0.w = *(unsigned*)&t;
    t = __floats2half2_rn(acc[8],  acc[9]);  u1.x = *(unsigned*)&t;
    t = __floats2half2_rn(acc[10], acc[11]); u1.y = *(unsigned*)&t;
    t = __floats2half2_rn(acc[12], acc[13]); u1.z = *(unsigned*)&t;
    t = __floats2half2_rn(acc[14], acc[15]); u1.w = *(unsigned*)&t;
    *(uint4*)(g_hh + (size_t)n * 8)     = u0;
    *(uint4*)(g_hh + (size_t)n * 8 + 4) = u1;

    float as[HEADS], ad[HEADS];
#pragma unroll
    for (int hh = 0; hh < HEADS; hh++) {
        as[hh] = acc[2 * hh] * s_att[2 * hh] + acc[2 * hh + 1] * s_att[2 * hh + 1];
        ad[hh] = acc[2 * hh] * s_att[HC + 2 * hh] + acc[2 * hh + 1] * s_att[HC + 2 * hh + 1];
    }
    *(float4*)(g_asrc + (size_t)n * HEADS)     = make_float4(as[0], as[1], as[2], as[3]);
    *(float4*)(g_asrc + (size_t)n * HEADS + 4) = make_float4(as[4], as[5], as[6], as[7]);
    *(float4*)(g_adst + (size_t)n * HEADS)     = make_float4(ad[0], ad[1], ad[2], ad[3]);
    *(float4*)(g_adst + (size_t)n * HEADS + 4) = make_float4(ad[4], ad[5], ad[6], ad[7]);

    float p[HEADS];
#pragma unroll
    for (int hh = 0; hh < HEADS; hh++) p[hh] = fexp(leaky(as[hh] + ad[hh]));

    float* accp = g_acc + (size_t)n * 24;
#pragma unroll
    for (int q = 0; q < 4; q++) {
        *(float4*)(accp + 4 * q) = make_float4(p[2 * q] * acc[4 * q],
                                               p[2 * q] * acc[4 * q + 1],
                                               p[2 * q + 1] * acc[4 * q + 2],
                                               p[2 * q + 1] * acc[4 * q + 3]);
    }
    *(float4*)(accp + 16) = make_float4(p[0], p[1], p[2], p[3]);
    *(float4*)(accp + 20) = make_float4(p[4], p[5], p[6], p[7]);
}

// -------- Kernel 1: per-node transform (2 nodes per thread, W in smem) --------
// W-row LDS amortized over 2 nodes; 4 CTAs/SM hide DRAM staging latency.
__global__ __launch_bounds__(NT, 4) void node_kernel(const float* __restrict__ x,
                                                     const float* __restrict__ W,
                                                     const float* __restrict__ att_src,
                                                     const float* __restrict__ att_dst,
                                                     int N) {
    __shared__ __align__(16) float Ws[IN_F * HC];   // 8KB
    __shared__ __align__(16) float xs[NPC * XPAD];  // 36.9KB
    __shared__ float s_att[2 * HC];

    int tid = threadIdx.x;
    int n0 = blockIdx.x * NPC;
    int na = n0 + 2 * tid;       // this thread's two nodes
    int nb = na + 1;

    {
        const float4* Wg = (const float4*)W;
        float4* Wsv = (float4*)Ws;
        for (int i = tid; i < IN_F * HC / 4; i += NT) Wsv[i] = Wg[i];
    }
    if (tid < HC) { s_att[tid] = att_src[tid]; s_att[HC + tid] = att_dst[tid]; }

    int valid = min(NPC, N - n0);

    float acc0[HC], acc1[HC];
#pragma unroll
    for (int j = 0; j < HC; j++) { acc0[j] = 0.f; acc1[j] = 0.f; }

#pragma unroll 1
    for (int kt = 0; kt < IN_F / KT; kt++) {
        __syncthreads();
        // Stage x[:, kt*32 .. +31] for NPC rows: 2048 float4, 16 per thread.
#pragma unroll
        for (int q = 0; q < 16; q++) {
            int idx = q * NT + tid;
            int r = idx >> 3, c = idx & 7;
            if (r < valid) {
                float4 v = *(const float4*)(x + (size_t)(n0 + r) * IN_F + kt * KT + c * 4);
                *(float4*)&xs[r * XPAD + c * 4] = v;
            }
        }
        __syncthreads();
        if (na < N) {
            const float* xr0 = &xs[(2 * tid) * XPAD];
            const float* xr1 = &xs[(2 * tid + 1) * XPAD];
#pragma unroll
            for (int q = 0; q < KT / 4; q++) {
                float4 xv0 = *(const float4*)&xr0[4 * q];
                float4 xv1 = *(const float4*)&xr1[4 * q];
                int kb = kt * KT + 4 * q;
                const float4* wr = (const float4*)&Ws[kb * HC];
#pragma unroll
                for (int kk = 0; kk < 4; kk++) {
                    float xk0 = (kk == 0) ? xv0.x : (kk == 1) ? xv0.y : (kk == 2) ? xv0.z : xv0.w;
                    float xk1 = (kk == 0) ? xv1.x : (kk == 1) ? xv1.y : (kk == 2) ? xv1.z : xv1.w;
                    float4 w0 = wr[kk * 4 + 0];
                    float4 w1 = wr[kk * 4 + 1];
                    float4 w2 = wr[kk * 4 + 2];
                    float4 w3 = wr[kk * 4 + 3];
                    acc0[0]  = fmaf(xk0, w0.x, acc0[0]);   acc1[0]  = fmaf(xk1, w0.x, acc1[0]);
                    acc0[1]  = fmaf(xk0, w0.y, acc0[1]);   acc1[1]  = fmaf(xk1, w0.y, acc1[1]);
                    acc0[2]  = fmaf(xk0, w0.z, acc0[2]);   acc1[2]  = fmaf(xk1, w0.z, acc1[2]);
                    acc0[3]  = fmaf(xk0, w0.w, acc0[3]);   acc1[3]  = fmaf(xk1, w0.w, acc1[3]);
                    acc0[4]  = fmaf(xk0, w1.x, acc0[4]);   acc1[4]  = fmaf(xk1, w1.x, acc1[4]);
                    acc0[5]  = fmaf(xk0, w1.y, acc0[5]);   acc1[5]  = fmaf(xk1, w1.y, acc1[5]);
                    acc0[6]  = fmaf(xk0, w1.z, acc0[6]);   acc1[6]  = fmaf(xk1, w1.z, acc1[6]);
                    acc0[7]  = fmaf(xk0, w1.w, acc0[7]);   acc1[7]  = fmaf(xk1, w1.w, acc1[7]);
                    acc0[8]  = fmaf(xk0, w2.x, acc0[8]);   acc1[8]  = fmaf(xk1, w2.x, acc1[8]);
                    acc0[9]  = fmaf(xk0, w2.y, acc0[9]);   acc1[9]  = fmaf(xk1, w2.y, acc1[9]);
                    acc0[10] = fmaf(xk0, w2.z, acc0[10]);  acc1[10] = fmaf(xk1, w2.z, acc1[10]);
                    acc0[11] = fmaf(xk0, w2.w, acc0[11]);  acc1[11] = fmaf(xk1, w2.w, acc1[11]);
                    acc0[12] = fmaf(xk0, w3.x, acc0[12]);  acc1[12] = fmaf(xk1, w3.x, acc1[12]);
                    acc0[13] = fmaf(xk0, w3.y, acc0[13]);  acc1[13] = fmaf(xk1, w3.y, acc1[13]);
                    acc0[14] = fmaf(xk0, w3.z, acc0[14]);  acc1[14] = fmaf(xk1, w3.z, acc1[14]);
                    acc0[15] = fmaf(xk0, w3.w, acc0[15]);  acc1[15] = fmaf(xk1, w3.w, acc1[15]);
                }
            }
        }
    }

    if (na < N) node_tail(na, acc0, s_att);
    if (nb < N) node_tail(nb, acc1, s_att);
}

// -------- Kernel 2: per-edge gather + fast-exp + scatter (vector red) --------
// Four threads per edge: thread q in {0..3} handles heads 2q, 2q+1.
__global__ __launch_bounds__(256) void edge_kernel(const int* __restrict__ ei, int E) {
    int t = blockIdx.x * blockDim.x + threadIdx.x;
    int e = t >> 2;
    if (e >= E) return;
    int q = t & 3;
    int s = __ldg(&ei[e]);
    int d = __ldg(&ei[E + e]);

    float2 a = *(const float2*)(g_asrc + (size_t)s * HEADS + 2 * q);
    float2 b = *(const float2*)(g_adst + (size_t)d * HEADS + 2 * q);
    float p0 = fexp(leaky(a.x + b.x));
    float p1 = fexp(leaky(a.y + b.y));

    uint2 hraw = *(const uint2*)(g_hh + (size_t)s * 8 + 2 * q);
    float2 f01 = __half22float2(*(__half2*)&hraw.x);
    float2 f23 = __half22float2(*(__half2*)&hraw.y);

    float* accp = g_acc + (size_t)d * 24;
    asm volatile("red.global.add.v4.f32 [%0], {%1, %2, %3, %4};"
                 :: "l"(accp + 4 * q),
                    "f"(p0 * f01.x), "f"(p0 * f01.y),
                    "f"(p1 * f23.x), "f"(p1 * f23.y) : "memory");

    float pp0 = __shfl_xor_sync(0xffffffffu, p0, 1);
    float pp1 = __shfl_xor_sync(0xffffffffu, p1, 1);
    if ((q & 1) == 0) {
        asm volatile("red.global.add.v4.f32 [%0], {%1, %2, %3, %4};"
                     :: "l"(accp + 16 + 2 * q),
                        "f"(p0), "f"(p1), "f"(pp0), "f"(pp1) : "memory");
    }
}

// -------- Kernel 3: normalize + bias + FC --------
__global__ __launch_bounds__(256) void out_kernel(const float* __restrict__ bias_gat,
                                                  const float* __restrict__ W_fc,
                                                  const float* __restrict__ b_fc,
                                                  float* __restrict__ out, int N) {
    int n = blockIdx.x * blockDim.x + threadIdx.x;
    if (n >= N) return;
    const float4* ap = (const float4*)(g_acc + (size_t)n * 24);
    float4 s0 = ap[0], s1 = ap[1], s2 = ap[2], s3 = ap[3];
    float4 z0 = ap[4], z1 = ap[5];
    float S[16] = { s0.x, s0.y, s0.z, s0.w, s1.x, s1.y, s1.z, s1.w,
                    s2.x, s2.y, s2.z, s2.w, s3.x, s3.y, s3.z, s3.w };
    float Z[8]  = { z0.x, z0.y, z0.z, z0.w, z1.x, z1.y, z1.z, z1.w };

    float o0 = __ldg(&b_fc[0]), o1 = __ldg(&b_fc[1]);
#pragma unroll
    for (int hh = 0; hh < 8; hh++) {
        float inv = 1.f / Z[hh];   // Z >= exp(self-loop) > 0 always
        float g0 = S[2 * hh] * inv + __ldg(&bias_gat[2 * hh]);
        float g1 = S[2 * hh + 1] * inv + __ldg(&bias_gat[2 * hh + 1]);
        o0 += g0 * __ldg(&W_fc[(2 * hh) * 2 + 0]) + g1 * __ldg(&W_fc[(2 * hh + 1) * 2 + 0]);
        o1 += g0 * __ldg(&W_fc[(2 * hh) * 2 + 1]) + g1 * __ldg(&W_fc[(2 * hh + 1) * 2 + 1]);
    }
    ((float2*)out)[n] = make_float2(o0, o1);
}

extern "C" void kernel_launch(void* const* d_in, const int* in_sizes, int n_in,
                              void* d_out, int out_size) {
    const float* x        = (const float*)d_in[0];
    const int*   ei       = (const int*)d_in[1];   // int32 (JAX x64 disabled)
    // d_in[2] = edge_attr: unused (GATConv built without edge_dim)
    const float* W        = (const float*)d_in[3];
    const float* att_src  = (const float*)d_in[4];
    const float* att_dst  = (const float*)d_in[5];
    const float* bias_gat = (const float*)d_in[6];
    const float* W_fc     = (const float*)d_in[7];
    const float* b_fc     = (const float*)d_in[8];

    int N = in_sizes[0] / IN_F;
    int E = in_sizes[1] / 2;

    node_kernel<<<(N + NPC - 1) / NPC, NT>>>(x, W, att_src, att_dst, N);
    long long tthreads = 4LL * E;
    edge_kernel<<<(int)((tthreads + 255) / 256), 256>>>(ei, E);
    out_kernel<<<(N + 255) / 256, 256>>>(bias_gat, W_fc, b_fc, (float*)d_out, N);
}